// round 10
// baseline (speedup 1.0000x reference)
#include <cuda_runtime.h>
#include <cuda_fp16.h>
#include <cstdint>

#define N_OUT 4096
#define M_IN  4096
#define BATCH 128
#define KTOT  4096
#define BN    128
#define SPLITK 8
#define KPER  (KTOT / SPLITK)   // 512
#define BK    64
#define KT    (KPER / BK)       // 8
#define STAGES 3
// stage: A 128x64 fp16 (16KB) + B 128x64 fp16 (16KB) = 32KB
#define STG_BYTES 32768
#define SMEM_BYTES (STAGES * STG_BYTES)   // 98304

// Scratch (device globals; no allocation allowed)
__device__ __align__(16) __half g_Wh[(size_t)N_OUT * M_IN];   // 32MB dense fp16 W
__device__ __align__(16) __half g_xh[BATCH * M_IN];           // x in fp16

// ---------------------------------------------------------------------------
__device__ __forceinline__ uint32_t smem_u32(const void* p) {
    return (uint32_t)__cvta_generic_to_shared(p);
}
__device__ __forceinline__ void cpasync16(uint32_t dst, const void* src) {
    asm volatile("cp.async.cg.shared.global [%0], [%1], 16;" :: "r"(dst), "l"(src));
}
__device__ __forceinline__ void ldsm4(uint32_t* r, uint32_t a) {
    asm volatile("ldmatrix.sync.aligned.m8n8.x4.shared.b16 {%0,%1,%2,%3}, [%4];"
                 : "=r"(r[0]), "=r"(r[1]), "=r"(r[2]), "=r"(r[3]) : "r"(a));
}
__device__ __forceinline__ void mma16816(float* c, const uint32_t* a, const uint32_t* b) {
    asm volatile(
        "mma.sync.aligned.m16n8k16.row.col.f32.f16.f16.f32 "
        "{%0,%1,%2,%3}, {%4,%5,%6,%7}, {%8,%9}, {%0,%1,%2,%3};"
        : "+f"(c[0]), "+f"(c[1]), "+f"(c[2]), "+f"(c[3])
        : "r"(a[0]), "r"(a[1]), "r"(a[2]), "r"(a[3]), "r"(b[0]), "r"(b[1]));
}
__device__ __forceinline__ void redv2(float* p, float x, float y) {
    asm volatile("red.global.add.v2.f32 [%0], {%1, %2};"
                 :: "l"(p), "f"(x), "f"(y) : "memory");
}

// ---------------------------------------------------------------------------
// K0 (fused): zero W, convert x -> fp16, init out with bias  (identical to R4)
// ---------------------------------------------------------------------------
__global__ void k_prep(const float* __restrict__ x,
                       const float* __restrict__ bias,
                       float* __restrict__ out) {
    const int gid = blockIdx.x * blockDim.x + threadIdx.x;
    const int nthr = gridDim.x * blockDim.x;

    uint4* wp = reinterpret_cast<uint4*>(g_Wh);
    uint4 z; z.x = 0; z.y = 0; z.z = 0; z.w = 0;
    const int n4 = (int)(((size_t)N_OUT * M_IN) / 8);
    for (int i = gid; i < n4; i += nthr) wp[i] = z;

    if (gid < (BATCH * M_IN) / 4) {
        const int idx = gid * 4;
        float4 v = *reinterpret_cast<const float4*>(x + idx);
        __half2* xp = reinterpret_cast<__half2*>(g_xh + idx);
        xp[0] = __floats2half2_rn(v.x, v.y);
        xp[1] = __floats2half2_rn(v.z, v.w);
        *reinterpret_cast<float4*>(out + idx) =
            *reinterpret_cast<const float4*>(bias + (idx & (N_OUT - 1)));
    }
}

// ---------------------------------------------------------------------------
// K1: scatter quantized values into dense fp16 W  (identical to R4)
// ---------------------------------------------------------------------------
__global__ void k_scatter(const int* __restrict__ val,
                          const int* __restrict__ rows,
                          const int* __restrict__ cols,
                          int nnz4) {
    int i = blockIdx.x * blockDim.x + threadIdx.x;
    if (i < nnz4) {
        int4 v = reinterpret_cast<const int4*>(val)[i];
        int4 r = reinterpret_cast<const int4*>(rows)[i];
        int4 c = reinterpret_cast<const int4*>(cols)[i];
        atomicAdd(&g_Wh[(size_t)r.x * M_IN + c.x], __float2half_rn((float)v.x));
        atomicAdd(&g_Wh[(size_t)r.y * M_IN + c.y], __float2half_rn((float)v.y));
        atomicAdd(&g_Wh[(size_t)r.z * M_IN + c.z], __float2half_rn((float)v.z));
        atomicAdd(&g_Wh[(size_t)r.w * M_IN + c.w], __float2half_rn((float)v.w));
    }
}

// ---------------------------------------------------------------------------
// K2: GEMM  out[b,n] += scale[n] * sum_k x_h[b,k] * W[n,k]
// CTA 128(batch) x 128(N), BK=64, 3-stage cp.async, split-K=8, 2 CTAs/SM.
// 8 warps as 2(m) x 4(n); warp tile 64x32 (mi<4 x ni<4 of m16n8k16).
// B fragments via ldsm4 (two per ks: (ni,h) 4-packs) instead of 4x ldsm2.
// smem stage: A[128][64] @ +0, B[128][64] @ +16KB; rows of 64 halves,
// 16B chunk c of row r stored at chunk (c ^ (r&7)).
// ---------------------------------------------------------------------------
__global__ void __launch_bounds__(256, 2)
k_gemm(const float* __restrict__ scales, float* __restrict__ out) {
    extern __shared__ __align__(1024) char smc[];

    const int tid  = threadIdx.x;
    const int lane = tid & 31;
    const int warp = tid >> 5;
    const int wm   = warp & 1;       // 0..1 -> 64-row M strip
    const int wn   = warp >> 1;      // 0..3 -> 32-col N strip
    const int bn0  = blockIdx.x * BN;
    const int kbase = blockIdx.y * KPER;

    float acc[4][4][4];
#pragma unroll
    for (int i = 0; i < 4; i++)
#pragma unroll
        for (int j = 0; j < 4; j++)
#pragma unroll
            for (int q = 0; q < 4; q++) acc[i][j][q] = 0.0f;

    // per-thread global->smem coords: 4 A chunks + 4 B chunks of 16B
    uint32_t aoff[4], boff[4];
    const __half* asrc[4];
    const __half* bsrc[4];
#pragma unroll
    for (int i = 0; i < 4; i++) {
        int q = tid + i * 256;           // 0..1023
        int r = q >> 3, c = q & 7;
        uint32_t sw = (r * 64 + ((c ^ (r & 7)) << 3)) * 2;
        aoff[i] = sw;
        boff[i] = 16384 + sw;
        asrc[i] = g_xh + r * M_IN + kbase + (c << 3);
        bsrc[i] = g_Wh + (size_t)(bn0 + r) * M_IN + kbase + (c << 3);
    }

    const uint32_t smb = smem_u32(smc);

    auto load_stage = [&](int s, int kofs) {
        uint32_t sb = smb + s * STG_BYTES;
#pragma unroll
        for (int i = 0; i < 4; i++) cpasync16(sb + aoff[i], asrc[i] + kofs);
#pragma unroll
        for (int i = 0; i < 4; i++) cpasync16(sb + boff[i], bsrc[i] + kofs);
    };

    // A fragment coords: row per mi, chunk = ks*2 + (lane>>4)
    int a_row[4];
#pragma unroll
    for (int mi = 0; mi < 4; mi++)
        a_row[mi] = wm * 64 + mi * 16 + (lane & 7) + ((lane >> 3) & 1) * 8;
    const int a_ch0 = lane >> 4;

    // B ldsm4 coords: call c covers ni = 2c,2c+1.
    // lane group g = lane>>3: ni = 2c + (g>>1), h = g&1, row = wn*32+ni*8+(lane&7)
    int b_row[2], b_h;
    {
        int g = lane >> 3;
        b_h = g & 1;
#pragma unroll
        for (int c = 0; c < 2; c++) {
            int ni = 2 * c + (g >> 1);
            b_row[c] = wn * 32 + ni * 8 + (lane & 7);
        }
    }

    // prologue: stages 0,1
    load_stage(0, 0);
    asm volatile("cp.async.commit_group;");
    load_stage(1, BK);
    asm volatile("cp.async.commit_group;");

    int slot = 0, wslot = 2;

#pragma unroll 1
    for (int kt = 0; kt < KT; ++kt) {
        asm volatile("cp.async.wait_group 1;");
        __syncthreads();

        if (kt + 2 < KT)
            load_stage(wslot, (kt + 2) * BK);
        asm volatile("cp.async.commit_group;");
        if (++wslot == STAGES) wslot = 0;

        const char* As = smc + slot * STG_BYTES;
        const char* Bs = As + 16384;
        if (++slot == STAGES) slot = 0;

#pragma unroll
        for (int ks = 0; ks < 4; ++ks) {
            uint32_t af[4][4];
#pragma unroll
            for (int mi = 0; mi < 4; mi++) {
                int row = a_row[mi];
                int ch  = ks * 2 + a_ch0;
                ldsm4(af[mi], smem_u32(As + (row * 64 + ((ch ^ (row & 7)) << 3)) * 2));
            }
            uint32_t bf[2][4];   // [call][4 regs]: regs 0,1 -> ni=2c; 2,3 -> ni=2c+1
#pragma unroll
            for (int c = 0; c < 2; c++) {
                int row = b_row[c];
                int ch  = ks * 2 + b_h;
                ldsm4(bf[c], smem_u32(Bs + (row * 64 + ((ch ^ (row & 7)) << 3)) * 2));
            }
#pragma unroll
            for (int ni = 0; ni < 4; ni++) {
                const uint32_t* bp = &bf[ni >> 1][(ni & 1) * 2];
#pragma unroll
                for (int mi = 0; mi < 4; mi++)
                    mma16816(acc[mi][ni], af[mi], bp);
            }
        }
    }

    // epilogue: scale + atomic add into bias-initialized out
#pragma unroll
    for (int ni = 0; ni < 4; ni++) {
        int nq = bn0 + wn * 32 + ni * 8 + ((lane & 3) << 1);
        float s0 = __ldg(scales + nq);
        float s1 = __ldg(scales + nq + 1);
#pragma unroll
        for (int mi = 0; mi < 4; mi++) {
            int r0 = wm * 64 + mi * 16 + (lane >> 2);
            redv2(out + (size_t)r0 * N_OUT + nq,
                  acc[mi][ni][0] * s0, acc[mi][ni][1] * s1);
            redv2(out + (size_t)(r0 + 8) * N_OUT + nq,
                  acc[mi][ni][2] * s0, acc[mi][ni][3] * s1);
        }
    }
}

// ---------------------------------------------------------------------------
extern "C" void kernel_launch(void* const* d_in, const int* in_sizes, int n_in,
                              void* d_out, int out_size) {
    const float* x    = (const float*)d_in[0];
    const int*   wval = (const int*)d_in[1];
    const float* wsc  = (const float*)d_in[2];
    const int*   rows = (const int*)d_in[3];
    const int*   cols = (const int*)d_in[4];
    const float* bias = (const float*)d_in[5];
    float* out = (float*)d_out;
    const int nnz = in_sizes[1];
    const int nnz4 = nnz / 4;

    cudaFuncSetAttribute(k_gemm, cudaFuncAttributeMaxDynamicSharedMemorySize, SMEM_BYTES);

    k_prep<<<4096, 256>>>(x, bias, out);
    k_scatter<<<(nnz4 + 255) / 256, 256>>>(wval, rows, cols, nnz4);
    k_gemm<<<dim3(N_OUT / BN, SPLITK), 256, SMEM_BYTES>>>(wsc, out);
}

// round 11
// speedup vs baseline: 1.0794x; 1.0794x over previous
#include <cuda_runtime.h>
#include <cuda_fp16.h>
#include <cstdint>

#define N_OUT 4096
#define M_IN  4096
#define BATCH 128
#define KTOT  4096
#define BN    64
#define SPLITK 4
#define KPER  (KTOT / SPLITK)   // 1024
#define BK    64
#define KT    (KPER / BK)       // 16
#define STAGES 4
// stage size in halves: A 128x64 + B 64x64 = 12288 halves (24KB)
#define STG_H 12288
#define SMEM_BYTES (STAGES * STG_H * 2)   // 98304

// Scratch (device globals; no allocation allowed)
__device__ __align__(16) __half g_Wh[(size_t)N_OUT * M_IN];   // 32MB dense fp16 W
__device__ __align__(16) __half g_xh[BATCH * M_IN];           // x in fp16

// ---------------------------------------------------------------------------
__device__ __forceinline__ uint32_t smem_u32(const void* p) {
    return (uint32_t)__cvta_generic_to_shared(p);
}
__device__ __forceinline__ void cpasync16(uint32_t dst, const void* src) {
    asm volatile("cp.async.cg.shared.global [%0], [%1], 16;" :: "r"(dst), "l"(src));
}
__device__ __forceinline__ void ldsm4(uint32_t* r, uint32_t a) {
    asm volatile("ldmatrix.sync.aligned.m8n8.x4.shared.b16 {%0,%1,%2,%3}, [%4];"
                 : "=r"(r[0]), "=r"(r[1]), "=r"(r[2]), "=r"(r[3]) : "r"(a));
}
__device__ __forceinline__ void ldsm2(uint32_t* r, uint32_t a) {
    asm volatile("ldmatrix.sync.aligned.m8n8.x2.shared.b16 {%0,%1}, [%2];"
                 : "=r"(r[0]), "=r"(r[1]) : "r"(a));
}
__device__ __forceinline__ void mma16816(float* c, const uint32_t* a, const uint32_t* b) {
    asm volatile(
        "mma.sync.aligned.m16n8k16.row.col.f32.f16.f16.f32 "
        "{%0,%1,%2,%3}, {%4,%5,%6,%7}, {%8,%9}, {%0,%1,%2,%3};"
        : "+f"(c[0]), "+f"(c[1]), "+f"(c[2]), "+f"(c[3])
        : "r"(a[0]), "r"(a[1]), "r"(a[2]), "r"(a[3]), "r"(b[0]), "r"(b[1]));
}
__device__ __forceinline__ void redv2(float* p, float x, float y) {
    asm volatile("red.global.add.v2.f32 [%0], {%1, %2};"
                 :: "l"(p), "f"(x), "f"(y) : "memory");
}

// ---------------------------------------------------------------------------
// K0: convert x -> fp16, init out with bias (W zero moved to cudaMemsetAsync)
// ---------------------------------------------------------------------------
__global__ void k_prep_lite(const float* __restrict__ x,
                            const float* __restrict__ bias,
                            float* __restrict__ out) {
    const int gid = blockIdx.x * blockDim.x + threadIdx.x;
    if (gid < (BATCH * M_IN) / 4) {
        const int idx = gid * 4;
        float4 v = *reinterpret_cast<const float4*>(x + idx);
        __half2* xp = reinterpret_cast<__half2*>(g_xh + idx);
        xp[0] = __floats2half2_rn(v.x, v.y);
        xp[1] = __floats2half2_rn(v.z, v.w);
        *reinterpret_cast<float4*>(out + idx) =
            *reinterpret_cast<const float4*>(bias + (idx & (N_OUT - 1)));
    }
}

// ---------------------------------------------------------------------------
// K1: scatter quantized values into dense fp16 W (identical to the 49.2 run)
// ---------------------------------------------------------------------------
__global__ void k_scatter(const int* __restrict__ val,
                          const int* __restrict__ rows,
                          const int* __restrict__ cols,
                          int nnz) {
    int i = blockIdx.x * blockDim.x + threadIdx.x;
    if (i < nnz) {
        int r = rows[i];
        int c = cols[i];
        atomicAdd(&g_Wh[(size_t)r * M_IN + c], __float2half_rn((float)val[i]));
    }
}

// ---------------------------------------------------------------------------
// K2: GEMM  out[b,n] += scale[n] * sum_k x_h[b,k] * W[n,k]
// (byte-identical to the 49.2 configuration)
// CTA tile 128(batch) x 64(N), BK=64, 4-stage cp.async, split-K=4.
// 8 warps as 4(m) x 2(n); warp tile 32x32 (mi<2 x ni<4 of m16n8k16).
// ---------------------------------------------------------------------------
__global__ void __launch_bounds__(256, 2)
k_gemm(const float* __restrict__ scales, float* __restrict__ out) {
    extern __shared__ __align__(1024) __half sm[];

    const int tid  = threadIdx.x;
    const int lane = tid & 31;
    const int warp = tid >> 5;
    const int wm   = warp & 3;       // 0..3  -> 32-row M strip
    const int wn   = warp >> 2;      // 0..1  -> 32-col N strip
    const int bn0  = blockIdx.x * BN;
    const int kbase = blockIdx.y * KPER;

    float acc[2][4][4];
#pragma unroll
    for (int i = 0; i < 2; i++)
#pragma unroll
        for (int j = 0; j < 4; j++)
#pragma unroll
            for (int q = 0; q < 4; q++) acc[i][j][q] = 0.0f;

    // per-thread load coords: 4 A chunks, 2 B chunks of 16B each
    uint32_t aoff[4], boff[2];
    const __half* asrc[4];
    const __half* bsrc[2];
#pragma unroll
    for (int i = 0; i < 4; i++) {
        int q = tid + i * 256;           // 0..1023
        int r = q >> 3, c = q & 7;
        aoff[i] = (r * 64 + ((c ^ (r & 7)) << 3)) * 2;   // byte offset
        asrc[i] = g_xh + r * M_IN + kbase + (c << 3);
    }
#pragma unroll
    for (int i = 0; i < 2; i++) {
        int q = tid + i * 256;           // 0..511
        int r = q >> 3, c = q & 7;
        boff[i] = (8192 + r * 64 + ((c ^ (r & 7)) << 3)) * 2;
        bsrc[i] = g_Wh + (size_t)(bn0 + r) * M_IN + kbase + (c << 3);
    }

    const uint32_t smb = smem_u32(sm);

    auto load_stage = [&](int s, int kofs) {
        uint32_t sb = smb + s * (STG_H * 2);
#pragma unroll
        for (int i = 0; i < 4; i++) cpasync16(sb + aoff[i], asrc[i] + kofs);
#pragma unroll
        for (int i = 0; i < 2; i++) cpasync16(sb + boff[i], bsrc[i] + kofs);
    };

    // prologue: stages 0..2
#pragma unroll
    for (int s = 0; s < STAGES - 1; s++) {
        load_stage(s, s * BK);
        asm volatile("cp.async.commit_group;");
    }

#pragma unroll 1
    for (int kt = 0; kt < KT; ++kt) {
        asm volatile("cp.async.wait_group %0;" :: "n"(STAGES - 2));
        __syncthreads();

        // issue loads for kt+3 (always commit to keep group count uniform)
        if (kt + STAGES - 1 < KT)
            load_stage((kt + STAGES - 1) & (STAGES - 1), (kt + STAGES - 1) * BK);
        asm volatile("cp.async.commit_group;");

        const __half* As = sm + (kt & (STAGES - 1)) * STG_H;
        const __half* Bs = As + 8192;

#pragma unroll
        for (int ks = 0; ks < 4; ++ks) {
            uint32_t af[2][4];
#pragma unroll
            for (int mi = 0; mi < 2; mi++) {
                int row = wm * 32 + mi * 16 + (lane & 7) + ((lane >> 3) & 1) * 8;
                int ch  = ks * 2 + (lane >> 4);
                ldsm4(af[mi], smem_u32(As + row * 64 + ((ch ^ (row & 7)) << 3)));
            }
#pragma unroll
            for (int ni = 0; ni < 4; ni++) {
                int rowb = wn * 32 + ni * 8 + (lane & 7);
                int chb  = ks * 2 + ((lane >> 3) & 1);
                uint32_t bf[2];
                ldsm2(bf, smem_u32(Bs + rowb * 64 + ((chb ^ (rowb & 7)) << 3)));
#pragma unroll
                for (int mi = 0; mi < 2; mi++)
                    mma16816(acc[mi][ni], af[mi], bf);
            }
        }
    }

    // epilogue: scale + atomic add into bias-initialized out
#pragma unroll
    for (int ni = 0; ni < 4; ni++) {
        int nq = bn0 + wn * 32 + ni * 8 + ((lane & 3) << 1);
        float s0 = __ldg(scales + nq);
        float s1 = __ldg(scales + nq + 1);
#pragma unroll
        for (int mi = 0; mi < 2; mi++) {
            int r0 = wm * 32 + mi * 16 + (lane >> 2);
            redv2(out + (size_t)r0 * N_OUT + nq,
                  acc[mi][ni][0] * s0, acc[mi][ni][1] * s1);
            redv2(out + (size_t)(r0 + 8) * N_OUT + nq,
                  acc[mi][ni][2] * s0, acc[mi][ni][3] * s1);
        }
    }
}

// ---------------------------------------------------------------------------
extern "C" void kernel_launch(void* const* d_in, const int* in_sizes, int n_in,
                              void* d_out, int out_size) {
    const float* x    = (const float*)d_in[0];
    const int*   wval = (const int*)d_in[1];
    const float* wsc  = (const float*)d_in[2];
    const int*   rows = (const int*)d_in[3];
    const int*   cols = (const int*)d_in[4];
    const float* bias = (const float*)d_in[5];
    float* out = (float*)d_out;
    const int nnz = in_sizes[1];

    cudaFuncSetAttribute(k_gemm, cudaFuncAttributeMaxDynamicSharedMemorySize, SMEM_BYTES);

    // zero W with the driver's memset node (graph-capturable, async)
    void* wptr = nullptr;
    cudaGetSymbolAddress(&wptr, g_Wh);
    cudaMemsetAsync(wptr, 0, (size_t)N_OUT * M_IN * sizeof(__half));

    k_prep_lite<<<(BATCH * M_IN / 4 + 255) / 256, 256>>>(x, bias, out);
    k_scatter<<<(nnz + 255) / 256, 256>>>(wval, rows, cols, nnz);
    k_gemm<<<dim3(N_OUT / BN, SPLITK), 256, SMEM_BYTES>>>(wsc, out);
}

// round 12
// speedup vs baseline: 1.1142x; 1.0323x over previous
#include <cuda_runtime.h>
#include <cuda_fp16.h>
#include <cstdint>

#define N_OUT 4096
#define M_IN  4096
#define BATCH 128
#define KTOT  4096
#define BN    64
#define SPLITK 4
#define KPER  (KTOT / SPLITK)   // 1024
#define BK    64
#define KT    (KPER / BK)       // 16
#define STAGES 4
// stage size in halves: A 128x64 + B 64x64 = 12288 halves (24KB)
#define STG_H 12288
#define SMEM_BYTES (STAGES * STG_H * 2)   // 98304

// Scratch (device globals; no allocation allowed)
__device__ __align__(16) __half g_Wh[(size_t)N_OUT * M_IN];   // 32MB dense fp16 W
__device__ __align__(16) __half g_xh[BATCH * M_IN];           // x in fp16

// ---------------------------------------------------------------------------
__device__ __forceinline__ uint32_t smem_u32(const void* p) {
    return (uint32_t)__cvta_generic_to_shared(p);
}
__device__ __forceinline__ void cpasync16(uint32_t dst, const void* src) {
    asm volatile("cp.async.cg.shared.global [%0], [%1], 16;" :: "r"(dst), "l"(src));
}
__device__ __forceinline__ void ldsm4(uint32_t* r, uint32_t a) {
    asm volatile("ldmatrix.sync.aligned.m8n8.x4.shared.b16 {%0,%1,%2,%3}, [%4];"
                 : "=r"(r[0]), "=r"(r[1]), "=r"(r[2]), "=r"(r[3]) : "r"(a));
}
__device__ __forceinline__ void ldsm2(uint32_t* r, uint32_t a) {
    asm volatile("ldmatrix.sync.aligned.m8n8.x2.shared.b16 {%0,%1}, [%2];"
                 : "=r"(r[0]), "=r"(r[1]) : "r"(a));
}
__device__ __forceinline__ void mma16816(float* c, const uint32_t* a, const uint32_t* b) {
    asm volatile(
        "mma.sync.aligned.m16n8k16.row.col.f32.f16.f16.f32 "
        "{%0,%1,%2,%3}, {%4,%5,%6,%7}, {%8,%9}, {%0,%1,%2,%3};"
        : "+f"(c[0]), "+f"(c[1]), "+f"(c[2]), "+f"(c[3])
        : "r"(a[0]), "r"(a[1]), "r"(a[2]), "r"(a[3]), "r"(b[0]), "r"(b[1]));
}
__device__ __forceinline__ void redv2(float* p, float x, float y) {
    asm volatile("red.global.add.v2.f32 [%0], {%1, %2};"
                 :: "l"(p), "f"(x), "f"(y) : "memory");
}

// ---------------------------------------------------------------------------
// K0 (fused): scatter quantized values into dense fp16 W (duplicates
// accumulate), AND (first 131072 threads) convert x->fp16 + init out=bias.
// W was zeroed by the preceding cudaMemsetAsync node.
// ---------------------------------------------------------------------------
__global__ void k_scatter_prep(const int* __restrict__ val,
                               const int* __restrict__ rows,
                               const int* __restrict__ cols,
                               int nnz,
                               const float* __restrict__ x,
                               const float* __restrict__ bias,
                               float* __restrict__ out) {
    const int gid = blockIdx.x * blockDim.x + threadIdx.x;

    if (gid < nnz) {
        int r = rows[gid];
        int c = cols[gid];
        atomicAdd(&g_Wh[(size_t)r * M_IN + c], __float2half_rn((float)val[gid]));
    }

    if (gid < (BATCH * M_IN) / 4) {
        const int idx = gid * 4;
        float4 v = *reinterpret_cast<const float4*>(x + idx);
        __half2* xp = reinterpret_cast<__half2*>(g_xh + idx);
        xp[0] = __floats2half2_rn(v.x, v.y);
        xp[1] = __floats2half2_rn(v.z, v.w);
        *reinterpret_cast<float4*>(out + idx) =
            *reinterpret_cast<const float4*>(bias + (idx & (N_OUT - 1)));
    }
}

// ---------------------------------------------------------------------------
// K1: GEMM  out[b,n] += scale[n] * sum_k x_h[b,k] * W[n,k]
// (byte-identical to the 49.2 configuration)
// CTA tile 128(batch) x 64(N), BK=64, 4-stage cp.async, split-K=4.
// 8 warps as 4(m) x 2(n); warp tile 32x32 (mi<2 x ni<4 of m16n8k16).
// ---------------------------------------------------------------------------
__global__ void __launch_bounds__(256, 2)
k_gemm(const float* __restrict__ scales, float* __restrict__ out) {
    extern __shared__ __align__(1024) __half sm[];

    const int tid  = threadIdx.x;
    const int lane = tid & 31;
    const int warp = tid >> 5;
    const int wm   = warp & 3;       // 0..3  -> 32-row M strip
    const int wn   = warp >> 2;      // 0..1  -> 32-col N strip
    const int bn0  = blockIdx.x * BN;
    const int kbase = blockIdx.y * KPER;

    float acc[2][4][4];
#pragma unroll
    for (int i = 0; i < 2; i++)
#pragma unroll
        for (int j = 0; j < 4; j++)
#pragma unroll
            for (int q = 0; q < 4; q++) acc[i][j][q] = 0.0f;

    // per-thread load coords: 4 A chunks, 2 B chunks of 16B each
    uint32_t aoff[4], boff[2];
    const __half* asrc[4];
    const __half* bsrc[2];
#pragma unroll
    for (int i = 0; i < 4; i++) {
        int q = tid + i * 256;           // 0..1023
        int r = q >> 3, c = q & 7;
        aoff[i] = (r * 64 + ((c ^ (r & 7)) << 3)) * 2;   // byte offset
        asrc[i] = g_xh + r * M_IN + kbase + (c << 3);
    }
#pragma unroll
    for (int i = 0; i < 2; i++) {
        int q = tid + i * 256;           // 0..511
        int r = q >> 3, c = q & 7;
        boff[i] = (8192 + r * 64 + ((c ^ (r & 7)) << 3)) * 2;
        bsrc[i] = g_Wh + (size_t)(bn0 + r) * M_IN + kbase + (c << 3);
    }

    const uint32_t smb = smem_u32(sm);

    auto load_stage = [&](int s, int kofs) {
        uint32_t sb = smb + s * (STG_H * 2);
#pragma unroll
        for (int i = 0; i < 4; i++) cpasync16(sb + aoff[i], asrc[i] + kofs);
#pragma unroll
        for (int i = 0; i < 2; i++) cpasync16(sb + boff[i], bsrc[i] + kofs);
    };

    // prologue: stages 0..2
#pragma unroll
    for (int s = 0; s < STAGES - 1; s++) {
        load_stage(s, s * BK);
        asm volatile("cp.async.commit_group;");
    }

#pragma unroll 1
    for (int kt = 0; kt < KT; ++kt) {
        asm volatile("cp.async.wait_group %0;" :: "n"(STAGES - 2));
        __syncthreads();

        // issue loads for kt+3 (always commit to keep group count uniform)
        if (kt + STAGES - 1 < KT)
            load_stage((kt + STAGES - 1) & (STAGES - 1), (kt + STAGES - 1) * BK);
        asm volatile("cp.async.commit_group;");

        const __half* As = sm + (kt & (STAGES - 1)) * STG_H;
        const __half* Bs = As + 8192;

#pragma unroll
        for (int ks = 0; ks < 4; ++ks) {
            uint32_t af[2][4];
#pragma unroll
            for (int mi = 0; mi < 2; mi++) {
                int row = wm * 32 + mi * 16 + (lane & 7) + ((lane >> 3) & 1) * 8;
                int ch  = ks * 2 + (lane >> 4);
                ldsm4(af[mi], smem_u32(As + row * 64 + ((ch ^ (row & 7)) << 3)));
            }
#pragma unroll
            for (int ni = 0; ni < 4; ni++) {
                int rowb = wn * 32 + ni * 8 + (lane & 7);
                int chb  = ks * 2 + ((lane >> 3) & 1);
                uint32_t bf[2];
                ldsm2(bf, smem_u32(Bs + rowb * 64 + ((chb ^ (rowb & 7)) << 3)));
#pragma unroll
                for (int mi = 0; mi < 2; mi++)
                    mma16816(acc[mi][ni], af[mi], bf);
            }
        }
    }

    // epilogue: scale + atomic add into bias-initialized out
#pragma unroll
    for (int ni = 0; ni < 4; ni++) {
        int nq = bn0 + wn * 32 + ni * 8 + ((lane & 3) << 1);
        float s0 = __ldg(scales + nq);
        float s1 = __ldg(scales + nq + 1);
#pragma unroll
        for (int mi = 0; mi < 2; mi++) {
            int r0 = wm * 32 + mi * 16 + (lane >> 2);
            redv2(out + (size_t)r0 * N_OUT + nq,
                  acc[mi][ni][0] * s0, acc[mi][ni][1] * s1);
            redv2(out + (size_t)(r0 + 8) * N_OUT + nq,
                  acc[mi][ni][2] * s0, acc[mi][ni][3] * s1);
        }
    }
}

// ---------------------------------------------------------------------------
extern "C" void kernel_launch(void* const* d_in, const int* in_sizes, int n_in,
                              void* d_out, int out_size) {
    const float* x    = (const float*)d_in[0];
    const int*   wval = (const int*)d_in[1];
    const float* wsc  = (const float*)d_in[2];
    const int*   rows = (const int*)d_in[3];
    const int*   cols = (const int*)d_in[4];
    const float* bias = (const float*)d_in[5];
    float* out = (float*)d_out;
    const int nnz = in_sizes[1];

    cudaFuncSetAttribute(k_gemm, cudaFuncAttributeMaxDynamicSharedMemorySize, SMEM_BYTES);

    // node 1: zero W via driver memset (graph-capturable, async)
    void* wptr = nullptr;
    cudaGetSymbolAddress(&wptr, g_Wh);
    cudaMemsetAsync(wptr, 0, (size_t)N_OUT * M_IN * sizeof(__half));

    // node 2: scatter + x->fp16 + out=bias (fused)
    k_scatter_prep<<<(nnz + 255) / 256, 256>>>(wval, rows, cols, nnz, x, bias, out);

    // node 3: tensor-core GEMM
    k_gemm<<<dim3(N_OUT / BN, SPLITK), 256, SMEM_BYTES>>>(wsc, out);
}

// round 13
// speedup vs baseline: 1.1236x; 1.0085x over previous
#include <cuda_runtime.h>
#include <cuda_fp16.h>
#include <cstdint>

#define N_OUT 4096
#define M_IN  4096
#define BATCH 128
#define KTOT  4096
#define BN    64
#define SPLITK 4
#define KPER  (KTOT / SPLITK)   // 1024
#define BK    64
#define KT    (KPER / BK)       // 16
#define STAGES 4
// stage size in halves: A 128x64 + B 64x64 = 12288 halves (24KB)
#define STG_H 12288
#define SMEM_BYTES (STAGES * STG_H * 2)   // 98304

// Scratch (device globals; no allocation allowed)
__device__ __align__(16) __half g_Wh[(size_t)N_OUT * M_IN];   // 32MB dense fp16 W
__device__ __align__(16) __half g_xh[BATCH * M_IN];           // x in fp16

// ---------------------------------------------------------------------------
__device__ __forceinline__ uint32_t smem_u32(const void* p) {
    return (uint32_t)__cvta_generic_to_shared(p);
}
__device__ __forceinline__ void cpasync16(uint32_t dst, const void* src) {
    asm volatile("cp.async.cg.shared.global [%0], [%1], 16;" :: "r"(dst), "l"(src));
}
__device__ __forceinline__ void ldsm4(uint32_t* r, uint32_t a) {
    asm volatile("ldmatrix.sync.aligned.m8n8.x4.shared.b16 {%0,%1,%2,%3}, [%4];"
                 : "=r"(r[0]), "=r"(r[1]), "=r"(r[2]), "=r"(r[3]) : "r"(a));
}
__device__ __forceinline__ void mma16816(float* c, const uint32_t* a, const uint32_t* b) {
    asm volatile(
        "mma.sync.aligned.m16n8k16.row.col.f32.f16.f16.f32 "
        "{%0,%1,%2,%3}, {%4,%5,%6,%7}, {%8,%9}, {%0,%1,%2,%3};"
        : "+f"(c[0]), "+f"(c[1]), "+f"(c[2]), "+f"(c[3])
        : "r"(a[0]), "r"(a[1]), "r"(a[2]), "r"(a[3]), "r"(b[0]), "r"(b[1]));
}
__device__ __forceinline__ void redv2(float* p, float x, float y) {
    asm volatile("red.global.add.v2.f32 [%0], {%1, %2};"
                 :: "l"(p), "f"(x), "f"(y) : "memory");
}

// ---------------------------------------------------------------------------
// K0 (fused): scatter quantized values into dense fp16 W (duplicates
// accumulate), AND (first 131072 threads) convert x->fp16 + init out=bias.
// W was zeroed by the preceding cudaMemsetAsync node.
// ---------------------------------------------------------------------------
__global__ void k_scatter_prep(const int* __restrict__ val,
                               const int* __restrict__ rows,
                               const int* __restrict__ cols,
                               int nnz,
                               const float* __restrict__ x,
                               const float* __restrict__ bias,
                               float* __restrict__ out) {
    const int gid = blockIdx.x * blockDim.x + threadIdx.x;

    if (gid < nnz) {
        int r = rows[gid];
        int c = cols[gid];
        atomicAdd(&g_Wh[(size_t)r * M_IN + c], __float2half_rn((float)val[gid]));
    }

    if (gid < (BATCH * M_IN) / 4) {
        const int idx = gid * 4;
        float4 v = *reinterpret_cast<const float4*>(x + idx);
        __half2* xp = reinterpret_cast<__half2*>(g_xh + idx);
        xp[0] = __floats2half2_rn(v.x, v.y);
        xp[1] = __floats2half2_rn(v.z, v.w);
        *reinterpret_cast<float4*>(out + idx) =
            *reinterpret_cast<const float4*>(bias + (idx & (N_OUT - 1)));
    }
}

// ---------------------------------------------------------------------------
// K1: GEMM  out[b,n] += scale[n] * sum_k x_h[b,k] * W[n,k]
// R4 configuration (BN=64, SPLITK=4, 4-stage, 2 CTAs/SM, warp tile 32x32)
// with ONE change: B fragments via 2x ldsm4 per ks instead of 4x ldsm2
// (lane group g -> matrix (ni = 2c + (g>>1), h = g&1)).
// ---------------------------------------------------------------------------
__global__ void __launch_bounds__(256, 2)
k_gemm(const float* __restrict__ scales, float* __restrict__ out) {
    extern __shared__ __align__(1024) __half sm[];

    const int tid  = threadIdx.x;
    const int lane = tid & 31;
    const int warp = tid >> 5;
    const int wm   = warp & 3;       // 0..3  -> 32-row M strip
    const int wn   = warp >> 2;      // 0..1  -> 32-col N strip
    const int bn0  = blockIdx.x * BN;
    const int kbase = blockIdx.y * KPER;

    float acc[2][4][4];
#pragma unroll
    for (int i = 0; i < 2; i++)
#pragma unroll
        for (int j = 0; j < 4; j++)
#pragma unroll
            for (int q = 0; q < 4; q++) acc[i][j][q] = 0.0f;

    // per-thread load coords: 4 A chunks, 2 B chunks of 16B each
    uint32_t aoff[4], boff[2];
    const __half* asrc[4];
    const __half* bsrc[2];
#pragma unroll
    for (int i = 0; i < 4; i++) {
        int q = tid + i * 256;           // 0..1023
        int r = q >> 3, c = q & 7;
        aoff[i] = (r * 64 + ((c ^ (r & 7)) << 3)) * 2;   // byte offset
        asrc[i] = g_xh + r * M_IN + kbase + (c << 3);
    }
#pragma unroll
    for (int i = 0; i < 2; i++) {
        int q = tid + i * 256;           // 0..511
        int r = q >> 3, c = q & 7;
        boff[i] = (8192 + r * 64 + ((c ^ (r & 7)) << 3)) * 2;
        bsrc[i] = g_Wh + (size_t)(bn0 + r) * M_IN + kbase + (c << 3);
    }

    const uint32_t smb = smem_u32(sm);

    auto load_stage = [&](int s, int kofs) {
        uint32_t sb = smb + s * (STG_H * 2);
#pragma unroll
        for (int i = 0; i < 4; i++) cpasync16(sb + aoff[i], asrc[i] + kofs);
#pragma unroll
        for (int i = 0; i < 2; i++) cpasync16(sb + boff[i], bsrc[i] + kofs);
    };

    // B ldsm4 fragment coords: call c covers ni = 2c, 2c+1.
    // lane group g = lane>>3: ni = 2c + (g>>1), h = g&1
    int b_row[2], b_h;
    {
        int g = lane >> 3;
        b_h = g & 1;
#pragma unroll
        for (int c = 0; c < 2; c++) {
            int ni = 2 * c + (g >> 1);
            b_row[c] = wn * 32 + ni * 8 + (lane & 7);
        }
    }

    // prologue: stages 0..2
#pragma unroll
    for (int s = 0; s < STAGES - 1; s++) {
        load_stage(s, s * BK);
        asm volatile("cp.async.commit_group;");
    }

#pragma unroll 1
    for (int kt = 0; kt < KT; ++kt) {
        asm volatile("cp.async.wait_group %0;" :: "n"(STAGES - 2));
        __syncthreads();

        // issue loads for kt+3 (always commit to keep group count uniform)
        if (kt + STAGES - 1 < KT)
            load_stage((kt + STAGES - 1) & (STAGES - 1), (kt + STAGES - 1) * BK);
        asm volatile("cp.async.commit_group;");

        const __half* As = sm + (kt & (STAGES - 1)) * STG_H;
        const __half* Bs = As + 8192;

#pragma unroll
        for (int ks = 0; ks < 4; ++ks) {
            uint32_t af[2][4];
#pragma unroll
            for (int mi = 0; mi < 2; mi++) {
                int row = wm * 32 + mi * 16 + (lane & 7) + ((lane >> 3) & 1) * 8;
                int ch  = ks * 2 + (lane >> 4);
                ldsm4(af[mi], smem_u32(As + row * 64 + ((ch ^ (row & 7)) << 3)));
            }
            uint32_t bf[2][4];   // [call][regs]: 0,1 -> ni=2c; 2,3 -> ni=2c+1
#pragma unroll
            for (int c = 0; c < 2; c++) {
                int row = b_row[c];
                int ch  = ks * 2 + b_h;
                ldsm4(bf[c], smem_u32(Bs + row * 64 + ((ch ^ (row & 7)) << 3)));
            }
#pragma unroll
            for (int ni = 0; ni < 4; ni++) {
                const uint32_t* bp = &bf[ni >> 1][(ni & 1) * 2];
#pragma unroll
                for (int mi = 0; mi < 2; mi++)
                    mma16816(acc[mi][ni], af[mi], bp);
            }
        }
    }

    // epilogue: scale + atomic add into bias-initialized out
#pragma unroll
    for (int ni = 0; ni < 4; ni++) {
        int nq = bn0 + wn * 32 + ni * 8 + ((lane & 3) << 1);
        float s0 = __ldg(scales + nq);
        float s1 = __ldg(scales + nq + 1);
#pragma unroll
        for (int mi = 0; mi < 2; mi++) {
            int r0 = wm * 32 + mi * 16 + (lane >> 2);
            redv2(out + (size_t)r0 * N_OUT + nq,
                  acc[mi][ni][0] * s0, acc[mi][ni][1] * s1);
            redv2(out + (size_t)(r0 + 8) * N_OUT + nq,
                  acc[mi][ni][2] * s0, acc[mi][ni][3] * s1);
        }
    }
}

// ---------------------------------------------------------------------------
extern "C" void kernel_launch(void* const* d_in, const int* in_sizes, int n_in,
                              void* d_out, int out_size) {
    const float* x    = (const float*)d_in[0];
    const int*   wval = (const int*)d_in[1];
    const float* wsc  = (const float*)d_in[2];
    const int*   rows = (const int*)d_in[3];
    const int*   cols = (const int*)d_in[4];
    const float* bias = (const float*)d_in[5];
    float* out = (float*)d_out;
    const int nnz = in_sizes[1];

    cudaFuncSetAttribute(k_gemm, cudaFuncAttributeMaxDynamicSharedMemorySize, SMEM_BYTES);

    // node 1: zero W via driver memset (graph-capturable, async)
    void* wptr = nullptr;
    cudaGetSymbolAddress(&wptr, g_Wh);
    cudaMemsetAsync(wptr, 0, (size_t)N_OUT * M_IN * sizeof(__half));

    // node 2: scatter + x->fp16 + out=bias (fused)
    k_scatter_prep<<<(nnz + 255) / 256, 256>>>(wval, rows, cols, nnz, x, bias, out);

    // node 3: tensor-core GEMM
    k_gemm<<<dim3(N_OUT / BN, SPLITK), 256, SMEM_BYTES>>>(wsc, out);
}